// round 10
// baseline (speedup 1.0000x reference)
#include <cuda_runtime.h>
#include <cuda_bf16.h>
#include <cstdint>

// ---------------------------------------------------------------------------
// ChildSumTreeLSTM depth 17, D=H=128. R10: register-pipelined HMMA gemm
// (fragment double-buffering, pass-major accumulator interleave), leaf
// reshaped to the same M=64 geometry, prefetched epilogue loads.
// ---------------------------------------------------------------------------

#define DEPTH   17
#define HH      128
#define NNODES  ((1 << (DEPTH + 1)) - 1)
#define PITCH   136

__device__ float g_h[33554304L];
__device__ float g_c[33554304L];
// weight images: [mat][hi 2048 uint4 | lo 2048 uint4], dense [k][n] bf16
// mats: 0..3 = W_i,W_f,W_o,W_u ; 4..7 = U_i,U_f,U_o,U_u
__device__ uint4 g_Wb[8][4096];

__device__ __forceinline__ float sigf(float v)  { return 1.0f / (1.0f + __expf(-v)); }
__device__ __forceinline__ float tanhx(float v) {
    float r; asm("tanh.approx.f32 %0, %1;" : "=f"(r) : "f"(v)); return r;
}
__device__ __forceinline__ uint32_t smem_u32(const void* p) {
    uint32_t a; asm("{ .reg .u64 t; cvta.to.shared.u64 t, %1; cvt.u32.u64 %0, t; }"
                    : "=r"(a) : "l"(p)); return a;
}
__device__ __forceinline__ void ldsm4(uint32_t& r0, uint32_t& r1, uint32_t& r2,
                                      uint32_t& r3, uint32_t a) {
    asm volatile("ldmatrix.sync.aligned.m8n8.x4.shared.b16 {%0,%1,%2,%3}, [%4];"
                 : "=r"(r0), "=r"(r1), "=r"(r2), "=r"(r3) : "r"(a));
}
__device__ __forceinline__ void ldsm4t(uint32_t& r0, uint32_t& r1, uint32_t& r2,
                                       uint32_t& r3, uint32_t a) {
    asm volatile("ldmatrix.sync.aligned.m8n8.x4.trans.shared.b16 {%0,%1,%2,%3}, [%4];"
                 : "=r"(r0), "=r"(r1), "=r"(r2), "=r"(r3) : "r"(a));
}
__device__ __forceinline__ void mma16816(float* c, uint32_t a0, uint32_t a1,
                                         uint32_t a2, uint32_t a3,
                                         uint32_t b0, uint32_t b1) {
    asm volatile("mma.sync.aligned.m16n8k16.row.col.f32.bf16.bf16.f32 "
                 "{%0,%1,%2,%3}, {%4,%5,%6,%7}, {%8,%9}, {%0,%1,%2,%3};"
                 : "+f"(c[0]), "+f"(c[1]), "+f"(c[2]), "+f"(c[3])
                 : "r"(a0), "r"(a1), "r"(a2), "r"(a3), "r"(b0), "r"(b1));
}
__device__ __forceinline__ void split2(float a, float b, uint32_t& hi, uint32_t& lo) {
    __nv_bfloat162 h = __floats2bfloat162_rn(a, b);
    float ra = a - __bfloat162float(__low2bfloat16(h));
    float rb = b - __bfloat162float(__high2bfloat16(h));
    __nv_bfloat162 l = __floats2bfloat162_rn(ra, rb);
    hi = *(uint32_t*)&h; lo = *(uint32_t*)&l;
}

// ---------------------------------------------------------------------------
// Register-pipelined 3-pass GEMM (NT=2 fixed). A/B fragments double-buffered;
// per kc: 12 MMAs interleaved pass-major (acc reuse distance 4).
//   ac[0..3]=A hi frags, ac[4..7]=A lo. bc[0..7]=j0 (hi,lo), bc[8..15]=j1.
// ---------------------------------------------------------------------------
__device__ __forceinline__ void gemm_P(float (*dacc)[4], uint32_t aH, uint32_t aL,
                                       uint32_t bH, uint32_t bL)
{
    uint32_t ac[8], an[8], bc[16], bn[16];
    ldsm4(ac[0],ac[1],ac[2],ac[3], aH);
    ldsm4(ac[4],ac[5],ac[6],ac[7], aL);
    ldsm4t(bc[0],bc[1],bc[2],bc[3],     bH);
    ldsm4t(bc[4],bc[5],bc[6],bc[7],     bL);
    ldsm4t(bc[8],bc[9],bc[10],bc[11],   bH + 32);
    ldsm4t(bc[12],bc[13],bc[14],bc[15], bL + 32);
#pragma unroll
    for (int kc = 0; kc < 8; ++kc) {
        if (kc < 7) {
            uint32_t aHn = aH + (kc+1)*32,             aLn = aL + (kc+1)*32;
            uint32_t bHn = bH + (kc+1)*(16*PITCH*2),   bLn = bL + (kc+1)*(16*PITCH*2);
            ldsm4(an[0],an[1],an[2],an[3], aHn);
            ldsm4(an[4],an[5],an[6],an[7], aLn);
            ldsm4t(bn[0],bn[1],bn[2],bn[3],     bHn);
            ldsm4t(bn[4],bn[5],bn[6],bn[7],     bLn);
            ldsm4t(bn[8],bn[9],bn[10],bn[11],   bHn + 32);
            ldsm4t(bn[12],bn[13],bn[14],bn[15], bLn + 32);
        }
        // pass hh
        mma16816(dacc[0], ac[0],ac[1],ac[2],ac[3], bc[0],  bc[1]);
        mma16816(dacc[2], ac[0],ac[1],ac[2],ac[3], bc[8],  bc[9]);
        mma16816(dacc[1], ac[0],ac[1],ac[2],ac[3], bc[2],  bc[3]);
        mma16816(dacc[3], ac[0],ac[1],ac[2],ac[3], bc[10], bc[11]);
        // pass hl (B lo)
        mma16816(dacc[0], ac[0],ac[1],ac[2],ac[3], bc[4],  bc[5]);
        mma16816(dacc[2], ac[0],ac[1],ac[2],ac[3], bc[12], bc[13]);
        mma16816(dacc[1], ac[0],ac[1],ac[2],ac[3], bc[6],  bc[7]);
        mma16816(dacc[3], ac[0],ac[1],ac[2],ac[3], bc[14], bc[15]);
        // pass lh (A lo)
        mma16816(dacc[0], ac[4],ac[5],ac[6],ac[7], bc[0],  bc[1]);
        mma16816(dacc[2], ac[4],ac[5],ac[6],ac[7], bc[8],  bc[9]);
        mma16816(dacc[1], ac[4],ac[5],ac[6],ac[7], bc[2],  bc[3]);
        mma16816(dacc[3], ac[4],ac[5],ac[6],ac[7], bc[10], bc[11]);
        if (kc < 7) {
#pragma unroll
            for (int i = 0; i < 8; ++i)  ac[i] = an[i];
#pragma unroll
            for (int i = 0; i < 16; ++i) bc[i] = bn[i];
        }
    }
}

// register-prefetch B staging (512-thread kernels): 4 hi + 4 lo uint4 / thread
__device__ __forceinline__ void ldB(uint4* r, int mat, int tid) {
    const uint4* src = g_Wb[mat];
#pragma unroll
    for (int q = 0; q < 4; ++q) {
        r[q]     = src[tid + q*512];
        r[q + 4] = src[tid + q*512 + 2048];
    }
}
__device__ __forceinline__ void stB(__nv_bfloat16* Bh, __nv_bfloat16* Bl,
                                    const uint4* r, int tid) {
#pragma unroll
    for (int q = 0; q < 4; ++q) {
        int i = tid + q*512, row = i >> 4, ch = i & 15;
        *(uint4*)(Bh + row*PITCH + ch*8) = r[q];
        *(uint4*)(Bl + row*PITCH + ch*8) = r[q + 4];
    }
}

__global__ void conv_w_kernel(
    const float* __restrict__ W_i, const float* __restrict__ W_f,
    const float* __restrict__ W_o, const float* __restrict__ W_u,
    const float* __restrict__ U_i, const float* __restrict__ U_f,
    const float* __restrict__ U_o, const float* __restrict__ U_u)
{
    const float* mats[8] = { W_i, W_f, W_o, W_u, U_i, U_f, U_o, U_u };
    const float* M = mats[blockIdx.x];
    __nv_bfloat16* hi = (__nv_bfloat16*)&g_Wb[blockIdx.x][0];
    __nv_bfloat16* lo = hi + 16384;
    for (int idx = threadIdx.x; idx < 16384; idx += blockDim.x) {
        float v = M[idx];
        __nv_bfloat16 h = __float2bfloat16(v);
        hi[idx] = h;
        lo[idx] = __float2bfloat16(v - __bfloat162float(h));
    }
}

// convert one fp32 row-half into bf16 hi/lo smem
__device__ __forceinline__ void conv_row(__nv_bfloat16* dh, __nv_bfloat16* dl,
                                         int row, int half,
                                         const float* __restrict__ s0,
                                         const float* __restrict__ s1)
{
#pragma unroll
    for (int i = 0; i < 16; ++i) {
        float4 v = *(const float4*)(s0 + i*4);
        if (s1) {
            float4 w = *(const float4*)(s1 + i*4);
            v.x += w.x; v.y += w.y; v.z += w.z; v.w += w.w;
        }
        uint32_t h0,l0,h1,l1;
        split2(v.x,v.y,h0,l0); split2(v.z,v.w,h1,l1);
        *(uint2*)(dh + row*PITCH + half + i*4) = make_uint2(h0,h1);
        *(uint2*)(dl + row*PITCH + half + i*4) = make_uint2(l0,l1);
    }
}

#define ZERO4 { _Pragma("unroll") for (int t = 0; t < 4; ++t) \
        { dacc[t][0]=0.f; dacc[t][1]=0.f; dacc[t][2]=0.f; dacc[t][3]=0.f; } }

// ---------------------------------------------------------------------------
// Leaf: 64 leaves/block, 512 threads (4 rowgrp x 4 colslice), pipelined gemm.
// smem: Xh,Xl (64*PITCH) + Bh,Bl (128*PITCH) = 104448 B -> 2 CTA/SM.
// ---------------------------------------------------------------------------
__global__ void __launch_bounds__(512) leaf_kernel(
    const float* __restrict__ x,
    const float* __restrict__ b_i, const float* __restrict__ b_o,
    const float* __restrict__ b_u)
{
    constexpr int AS = 64 * PITCH;
    extern __shared__ __align__(16) __nv_bfloat16 sm[];
    __nv_bfloat16* Xh = sm;
    __nv_bfloat16* Xl = sm + AS;
    __nv_bfloat16* Bh = sm + 2*AS;
    __nv_bfloat16* Bl = sm + 2*AS + 128*PITCH;

    const int tid = threadIdx.x;
    const int w = tid >> 5, l = tid & 31;
    const int mg = w >> 2, nh = w & 3;
    const int lr = l & 15, lc = l >> 4;
    const int qr = l >> 2, qc2 = (l & 3) * 2;
    const long np = (long)((1 << DEPTH) - 1) + (long)blockIdx.x * 64;

    uint4 breg[8];
    ldB(breg, 3, tid);                      // W_u
    if (tid < 128) {
        int row = tid >> 1, half = (tid & 1) * 64;
        conv_row(Xh, Xl, row, half, x + (np + row)*HH + half, nullptr);
    }
    stB(Bh, Bl, breg, tid);
    __syncthreads();

    const uint32_t a_off = (uint32_t)((16*mg + lr)*PITCH + lc*8)*2;
    const uint32_t b_off = (uint32_t)(lr*PITCH + nh*32 + lc*8)*2;
    const uint32_t xH = smem_u32(Xh)+a_off, xL = smem_u32(Xl)+a_off;
    const uint32_t bH = smem_u32(Bh)+b_off, bL = smem_u32(Bl)+b_off;

    const long n0 = np + 16*mg + qr, n1 = n0 + 8;
    const int cbase = nh*32 + qc2;

    float dacc[4][4], cc[4][4];
#define SWAPB() do { __syncthreads(); stB(Bh, Bl, breg, tid); __syncthreads(); } while (0)

    ldB(breg, 0, tid);                      // W_i prefetch
    ZERO4; gemm_P(dacc, xH, xL, bH, bL);    // x @ W_u
#pragma unroll
    for (int t = 0; t < 4; ++t) {
        float2 b = *(const float2*)(b_u + cbase + t*8);
        cc[t][0]=tanhx(dacc[t][0]+b.x); cc[t][1]=tanhx(dacc[t][1]+b.y);
        cc[t][2]=tanhx(dacc[t][2]+b.x); cc[t][3]=tanhx(dacc[t][3]+b.y);
    }
    SWAPB();                                // B = W_i
    ldB(breg, 2, tid);                      // W_o prefetch
    ZERO4; gemm_P(dacc, xH, xL, bH, bL);
#pragma unroll
    for (int t = 0; t < 4; ++t) {
        float2 b = *(const float2*)(b_i + cbase + t*8);
        cc[t][0]*=sigf(dacc[t][0]+b.x); cc[t][1]*=sigf(dacc[t][1]+b.y);
        cc[t][2]*=sigf(dacc[t][2]+b.x); cc[t][3]*=sigf(dacc[t][3]+b.y);
    }
    SWAPB();                                // B = W_o
    ZERO4; gemm_P(dacc, xH, xL, bH, bL);
#pragma unroll
    for (int t = 0; t < 4; ++t) {
        int c = cbase + t*8;
        float2 b = *(const float2*)(b_o + c);
        float h0 = sigf(dacc[t][0]+b.x)*tanhx(cc[t][0]);
        float h1 = sigf(dacc[t][1]+b.y)*tanhx(cc[t][1]);
        float h2 = sigf(dacc[t][2]+b.x)*tanhx(cc[t][2]);
        float h3 = sigf(dacc[t][3]+b.y)*tanhx(cc[t][3]);
        *(float2*)(g_c + n0*HH + c) = make_float2(cc[t][0], cc[t][1]);
        *(float2*)(g_c + n1*HH + c) = make_float2(cc[t][2], cc[t][3]);
        *(float2*)(g_h + n0*HH + c) = make_float2(h0, h1);
        *(float2*)(g_h + n1*HH + c) = make_float2(h2, h3);
    }
#undef SWAPB
}

// ---------------------------------------------------------------------------
// Tensor level kernel: 64 parents/block, 512 threads, pipelined gemm.
// A slots: X, SUM (h0+h1), S1 (h1). smem 174080 B -> 1 CTA/SM.
// ---------------------------------------------------------------------------
__global__ void __launch_bounds__(512) tlevel_kernel(
    int sl, const float* __restrict__ x,
    const float* __restrict__ b_i, const float* __restrict__ b_f,
    const float* __restrict__ b_o, const float* __restrict__ b_u)
{
    constexpr int AS = 64 * PITCH;
    extern __shared__ __align__(16) __nv_bfloat16 sm[];
    __nv_bfloat16* Xh  = sm;
    __nv_bfloat16* Xl  = sm + AS;
    __nv_bfloat16* SUh = sm + 2*AS;
    __nv_bfloat16* SUl = sm + 3*AS;
    __nv_bfloat16* S1h = sm + 4*AS;
    __nv_bfloat16* S1l = sm + 5*AS;
    __nv_bfloat16* Bh  = sm + 6*AS;
    __nv_bfloat16* Bl  = sm + 6*AS + 128*PITCH;

    const int tid = threadIdx.x;
    const int w = tid >> 5, l = tid & 31;
    const int mg = w >> 2, nh = w & 3;
    const int lr = l & 15, lc = l >> 4;
    const int qr = l >> 2, qc2 = (l & 3) * 2;

    const long np = (long)sl + (long)blockIdx.x * 64;
    const long cb = 2*np + 1;

    uint4 breg[8];
    ldB(breg, 3, tid);                      // W_u
    if (tid < 384) {
        int slot = tid >> 7;                // 0=X, 1=SUM, 2=S1
        int row  = (tid & 127) >> 1;
        int half = (tid & 1) * 64;
        if (slot == 0)
            conv_row(Xh, Xl, row, half, x + (np + row)*HH + half, nullptr);
        else if (slot == 1)
            conv_row(SUh, SUl, row, half, g_h + (cb + 2*row)*HH + half,
                                          g_h + (cb + 2*row + 1)*HH + half);
        else
            conv_row(S1h, S1l, row, half, g_h + (cb + 2*row + 1)*HH + half, nullptr);
    }
    stB(Bh, Bl, breg, tid);
    __syncthreads();

    const uint32_t a_off = (uint32_t)((16*mg + lr)*PITCH + lc*8)*2;
    const uint32_t b_off = (uint32_t)(lr*PITCH + nh*32 + lc*8)*2;
    const uint32_t xH  = smem_u32(Xh)+a_off,  xL  = smem_u32(Xl)+a_off;
    const uint32_t suH = smem_u32(SUh)+a_off, suL = smem_u32(SUl)+a_off;
    const uint32_t s1H = smem_u32(S1h)+a_off, s1L = smem_u32(S1l)+a_off;
    const uint32_t bH  = smem_u32(Bh)+b_off,  bL  = smem_u32(Bl)+b_off;

    const long n0 = np + 16*mg + qr, n1 = n0 + 8;
    const int cbase = nh*32 + qc2;

    float dacc[4][4], cc[4][4], xf[4][4];
#define SWAPB() do { __syncthreads(); stB(Bh, Bl, breg, tid); __syncthreads(); } while (0)

    // ---- u ----
    ldB(breg, 7, tid);                      // U_u
    ZERO4; gemm_P(dacc, xH, xL, bH, bL);
    SWAPB();                                // B = U_u
    ldB(breg, 0, tid);                      // W_i
    gemm_P(dacc, suH, suL, bH, bL);
#pragma unroll
    for (int t = 0; t < 4; ++t) {
        float2 b = *(const float2*)(b_u + cbase + t*8);
        cc[t][0]=tanhx(dacc[t][0]+b.x); cc[t][1]=tanhx(dacc[t][1]+b.y);
        cc[t][2]=tanhx(dacc[t][2]+b.x); cc[t][3]=tanhx(dacc[t][3]+b.y);
    }
    // ---- i ----
    SWAPB();                                // B = W_i
    ldB(breg, 4, tid);                      // U_i
    ZERO4; gemm_P(dacc, xH, xL, bH, bL);
    SWAPB();                                // B = U_i
    ldB(breg, 1, tid);                      // W_f
    gemm_P(dacc, suH, suL, bH, bL);
#pragma unroll
    for (int t = 0; t < 4; ++t) {
        float2 b = *(const float2*)(b_i + cbase + t*8);
        cc[t][0]*=sigf(dacc[t][0]+b.x); cc[t][1]*=sigf(dacc[t][1]+b.y);
        cc[t][2]*=sigf(dacc[t][2]+b.x); cc[t][3]*=sigf(dacc[t][3]+b.y);
    }
    // ---- f ----
    SWAPB();                                // B = W_f
    ldB(breg, 5, tid);                      // U_f
    ZERO4; gemm_P(dacc, xH, xL, bH, bL);
#pragma unroll
    for (int t = 0; t < 4; ++t) {
        float2 b = *(const float2*)(b_f + cbase + t*8);
        xf[t][0]=dacc[t][0]+b.x; xf[t][1]=dacc[t][1]+b.y;
        xf[t][2]=dacc[t][2]+b.x; xf[t][3]=dacc[t][3]+b.y;
    }
    SWAPB();                                // B = U_f
    ldB(breg, 2, tid);                      // W_o (early: U_f used twice)
    {
        // prefetch child1 cells ahead of G1 gemm
        float2 ca1[4], cb1[4];
#pragma unroll
        for (int t = 0; t < 4; ++t) {
            int c = cbase + t*8;
            ca1[t] = *(const float2*)(g_c + (2*n0+2)*HH + c);
            cb1[t] = *(const float2*)(g_c + (2*n1+2)*HH + c);
        }
        ZERO4; gemm_P(dacc, s1H, s1L, bH, bL);   // G1 = h1 @ U_f
#pragma unroll
        for (int t = 0; t < 4; ++t) {
            cc[t][0]+=sigf(dacc[t][0]+xf[t][0])*ca1[t].x;
            cc[t][1]+=sigf(dacc[t][1]+xf[t][1])*ca1[t].y;
            cc[t][2]+=sigf(dacc[t][2]+xf[t][2])*cb1[t].x;
            cc[t][3]+=sigf(dacc[t][3]+xf[t][3])*cb1[t].y;
            dacc[t][0]=-dacc[t][0]; dacc[t][1]=-dacc[t][1];
            dacc[t][2]=-dacc[t][2]; dacc[t][3]=-dacc[t][3];
        }
    }
    {
        float2 ca0[4], cb0[4];
#pragma unroll
        for (int t = 0; t < 4; ++t) {
            int c = cbase + t*8;
            ca0[t] = *(const float2*)(g_c + (2*n0+1)*HH + c);
            cb0[t] = *(const float2*)(g_c + (2*n1+1)*HH + c);
        }
        gemm_P(dacc, suH, suL, bH, bL);          // Gsum - G1 = h0 @ U_f
#pragma unroll
        for (int t = 0; t < 4; ++t) {
            cc[t][0]+=sigf(dacc[t][0]+xf[t][0])*ca0[t].x;
            cc[t][1]+=sigf(dacc[t][1]+xf[t][1])*ca0[t].y;
            cc[t][2]+=sigf(dacc[t][2]+xf[t][2])*cb0[t].x;
            cc[t][3]+=sigf(dacc[t][3]+xf[t][3])*cb0[t].y;
        }
    }
    // ---- o + store ----
    SWAPB();                                // B = W_o
    ldB(breg, 6, tid);                      // U_o
    ZERO4; gemm_P(dacc, xH, xL, bH, bL);
    SWAPB();                                // B = U_o
    gemm_P(dacc, suH, suL, bH, bL);
#pragma unroll
    for (int t = 0; t < 4; ++t) {
        int c = cbase + t*8;
        float2 b = *(const float2*)(b_o + c);
        float h0 = sigf(dacc[t][0]+b.x)*tanhx(cc[t][0]);
        float h1 = sigf(dacc[t][1]+b.y)*tanhx(cc[t][1]);
        float h2 = sigf(dacc[t][2]+b.x)*tanhx(cc[t][2]);
        float h3 = sigf(dacc[t][3]+b.y)*tanhx(cc[t][3]);
        *(float2*)(g_c + n0*HH + c) = make_float2(cc[t][0], cc[t][1]);
        *(float2*)(g_c + n1*HH + c) = make_float2(cc[t][2], cc[t][3]);
        *(float2*)(g_h + n0*HH + c) = make_float2(h0, h1);
        *(float2*)(g_h + n1*HH + c) = make_float2(h2, h3);
    }
#undef SWAPB
}

// ---------------------------------------------------------------------------
// Small levels (nl < 64): one parent/block, 512 threads, 9 k-split matvecs.
// ---------------------------------------------------------------------------
__global__ void __launch_bounds__(512) small_level_kernel(
    int sl, const float* __restrict__ x,
    const float* __restrict__ W_i, const float* __restrict__ b_i, const float* __restrict__ U_i,
    const float* __restrict__ W_f, const float* __restrict__ b_f, const float* __restrict__ U_f,
    const float* __restrict__ W_o, const float* __restrict__ b_o, const float* __restrict__ U_o,
    const float* __restrict__ W_u, const float* __restrict__ b_u, const float* __restrict__ U_u)
{
    extern __shared__ float smf[];
    float* hs   = smf;              // [h~ | h0 | h1 | x] x 128
    float* part = smf + 512;        // [9][4][128]

    const int t = threadIdx.x;
    const long node = sl + blockIdx.x;
    const long ch0  = 2*node + 1;

    if (t < 128) {
        float h0 = g_h[ch0*HH + t];
        float h1 = g_h[(ch0+1)*HH + t];
        hs[128+t] = h0; hs[256+t] = h1; hs[t] = h0 + h1;
        hs[384+t] = x[node*HH + t];
    }
    __syncthreads();

    const int col = t & 127;
    const int q   = t >> 7;
    const int kb  = q * 32;

#define JOB(J, S, M) { float av = 0.f; const float* s = hs + (S)*128;          \
        _Pragma("unroll 8")                                                    \
        for (int k = 0; k < 32; ++k) av += s[kb+k] * (M)[(kb+k)*HH + col];     \
        part[((J)*4 + q)*128 + col] = av; }
    JOB(0, 0, U_i) JOB(1, 0, U_o) JOB(2, 0, U_u)
    JOB(3, 1, U_f) JOB(4, 2, U_f)
    JOB(5, 3, W_i) JOB(6, 3, W_f) JOB(7, 3, W_o) JOB(8, 3, W_u)
#undef JOB
    __syncthreads();

    if (t < 128) {
#define SUMP(J) (part[((J)*4+0)*128+t] + part[((J)*4+1)*128+t] + \
                 part[((J)*4+2)*128+t] + part[((J)*4+3)*128+t])
        float yi  = SUMP(0), yo = SUMP(1), yu = SUMP(2);
        float yf0 = SUMP(3), yf1 = SUMP(4);
        float xi  = SUMP(5) + b_i[t];
        float xfv = SUMP(6) + b_f[t];
        float xo  = SUMP(7) + b_o[t];
        float xu  = SUMP(8) + b_u[t];
#undef SUMP
        float c = sigf(xi+yi)*tanhx(xu+yu)
                + sigf(xfv+yf0)*g_c[ch0*HH+t] + sigf(xfv+yf1)*g_c[(ch0+1)*HH+t];
        g_c[node*HH+t] = c;
        g_h[node*HH+t] = sigf(xo+yo)*tanhx(c);
    }
}

__global__ void out_kernel(float* __restrict__ out)
{
    int t = threadIdx.x;
    out[t] = (t < 128) ? g_h[t] : g_c[t - 128];
}

// ---------------------------------------------------------------------------
extern "C" void kernel_launch(void* const* d_in, const int* in_sizes, int n_in,
                              void* d_out, int out_size)
{
    const float* x   = (const float*)d_in[0];
    const float* W_i = (const float*)d_in[1];
    const float* b_i = (const float*)d_in[2];
    const float* U_i = (const float*)d_in[3];
    const float* W_f = (const float*)d_in[4];
    const float* b_f = (const float*)d_in[5];
    const float* U_f = (const float*)d_in[6];
    const float* W_o = (const float*)d_in[7];
    const float* b_o = (const float*)d_in[8];
    const float* U_o = (const float*)d_in[9];
    const float* W_u = (const float*)d_in[10];
    const float* b_u = (const float*)d_in[11];
    const float* U_u = (const float*)d_in[12];

    const int SMEM_T = (6*64*PITCH + 2*128*PITCH) * 2;   // 174080
    const int SMEM_L = (2*64*PITCH + 2*128*PITCH) * 2;   // 104448
    const int SMEM_S = (512 + 9*4*128) * 4;
    cudaFuncSetAttribute(tlevel_kernel, cudaFuncAttributeMaxDynamicSharedMemorySize, SMEM_T);
    cudaFuncSetAttribute(leaf_kernel,   cudaFuncAttributeMaxDynamicSharedMemorySize, SMEM_L);
    cudaFuncSetAttribute(small_level_kernel, cudaFuncAttributeMaxDynamicSharedMemorySize, SMEM_S);

    conv_w_kernel<<<8, 256>>>(W_i, W_f, W_o, W_u, U_i, U_f, U_o, U_u);

    leaf_kernel<<<(1 << DEPTH) / 64, 512, SMEM_L>>>(x, b_i, b_o, b_u);

    for (int l = DEPTH - 1; l >= 0; --l) {
        int nl = 1 << l;
        int sl = nl - 1;
        if (nl >= 64)
            tlevel_kernel<<<nl / 64, 512, SMEM_T>>>(sl, x, b_i, b_f, b_o, b_u);
        else
            small_level_kernel<<<nl, 512, SMEM_S>>>(sl, x,
                W_i, b_i, U_i, W_f, b_f, U_f, W_o, b_o, U_o, W_u, b_u, U_u);
    }

    out_kernel<<<1, 256>>>((float*)d_out);
}

// round 11
// speedup vs baseline: 1.3447x; 1.3447x over previous
#include <cuda_runtime.h>
#include <cuda_fp16.h>
#include <cstdint>

// ---------------------------------------------------------------------------
// ChildSumTreeLSTM depth 17, D=H=128. R11: fp16 HMMA 2-pass split (A=hi+lo
// fp16, B=fp16), M=32 blocks with 256 threads and 2 CTAs/SM so staging /
// barrier phases of one CTA overlap MMA of the other.
// ---------------------------------------------------------------------------

#define DEPTH   17
#define HH      128
#define NNODES  ((1 << (DEPTH + 1)) - 1)
#define PITCH   136

__device__ float g_h[33554304L];
__device__ float g_c[33554304L];
// fp16 weight images, dense [k][n], 128x128 = 2048 uint4 each.
// mats: 0..3 = W_i,W_f,W_o,W_u ; 4..7 = U_i,U_f,U_o,U_u
__device__ uint4 g_Wh[8][2048];

__device__ __forceinline__ float sigf(float v)  { return 1.0f / (1.0f + __expf(-v)); }
__device__ __forceinline__ float tanhx(float v) {
    float r; asm("tanh.approx.f32 %0, %1;" : "=f"(r) : "f"(v)); return r;
}
__device__ __forceinline__ uint32_t smem_u32(const void* p) {
    uint32_t a; asm("{ .reg .u64 t; cvta.to.shared.u64 t, %1; cvt.u32.u64 %0, t; }"
                    : "=r"(a) : "l"(p)); return a;
}
__device__ __forceinline__ void ldsm4(uint32_t& r0, uint32_t& r1, uint32_t& r2,
                                      uint32_t& r3, uint32_t a) {
    asm volatile("ldmatrix.sync.aligned.m8n8.x4.shared.b16 {%0,%1,%2,%3}, [%4];"
                 : "=r"(r0), "=r"(r1), "=r"(r2), "=r"(r3) : "r"(a));
}
__device__ __forceinline__ void ldsm4t(uint32_t& r0, uint32_t& r1, uint32_t& r2,
                                       uint32_t& r3, uint32_t a) {
    asm volatile("ldmatrix.sync.aligned.m8n8.x4.trans.shared.b16 {%0,%1,%2,%3}, [%4];"
                 : "=r"(r0), "=r"(r1), "=r"(r2), "=r"(r3) : "r"(a));
}
__device__ __forceinline__ void mmaH(float* c, uint32_t a0, uint32_t a1,
                                     uint32_t a2, uint32_t a3,
                                     uint32_t b0, uint32_t b1) {
    asm volatile("mma.sync.aligned.m16n8k16.row.col.f32.f16.f16.f32 "
                 "{%0,%1,%2,%3}, {%4,%5,%6,%7}, {%8,%9}, {%0,%1,%2,%3};"
                 : "+f"(c[0]), "+f"(c[1]), "+f"(c[2]), "+f"(c[3])
                 : "r"(a0), "r"(a1), "r"(a2), "r"(a3), "r"(b0), "r"(b1));
}
// split two fp32 into fp16x2 hi + residual-lo words
__device__ __forceinline__ void split2h(float a, float b, uint32_t& hi, uint32_t& lo) {
    __half2 h = __floats2half2_rn(a, b);
    float ra = a - __low2float(h);
    float rb = b - __high2float(h);
    __half2 l = __floats2half2_rn(ra, rb);
    hi = *(uint32_t*)&h; lo = *(uint32_t*)&l;
}

// ---------------------------------------------------------------------------
// fp16 2-pass GEMM: dacc[4][4] += (A_hi + A_lo) @ B. Warp: 16 rows x 32 cols.
// Per kc: 2 A ldsm4 + 2 B ldsm4t + 8 MMA (acc reuse distance 4).
// ---------------------------------------------------------------------------
__device__ __forceinline__ void gemm_H(float (*dacc)[4], uint32_t aH, uint32_t aL,
                                       uint32_t bB)
{
#pragma unroll
    for (int kc = 0; kc < 8; ++kc) {
        uint32_t ah0,ah1,ah2,ah3, al0,al1,al2,al3;
        ldsm4(ah0,ah1,ah2,ah3, aH + kc*32);
        ldsm4(al0,al1,al2,al3, aL + kc*32);
        uint32_t bp = bB + kc*(16*PITCH*2);
        uint32_t b0,b1,b2,b3, b4,b5,b6,b7;
        ldsm4t(b0,b1,b2,b3, bp);
        ldsm4t(b4,b5,b6,b7, bp + 32);
        mmaH(dacc[0], ah0,ah1,ah2,ah3, b0,b1);
        mmaH(dacc[1], ah0,ah1,ah2,ah3, b2,b3);
        mmaH(dacc[2], ah0,ah1,ah2,ah3, b4,b5);
        mmaH(dacc[3], ah0,ah1,ah2,ah3, b6,b7);
        mmaH(dacc[0], al0,al1,al2,al3, b0,b1);
        mmaH(dacc[1], al0,al1,al2,al3, b2,b3);
        mmaH(dacc[2], al0,al1,al2,al3, b4,b5);
        mmaH(dacc[3], al0,al1,al2,al3, b6,b7);
    }
}

// register-prefetch B staging (256-thread kernels): 8 uint4 / thread
__device__ __forceinline__ void ldB8(uint4* r, int mat, int tid) {
    const uint4* src = g_Wh[mat];
#pragma unroll
    for (int q = 0; q < 8; ++q) r[q] = src[tid + q*256];
}
__device__ __forceinline__ void stB8(__half* Bp, const uint4* r, int tid) {
#pragma unroll
    for (int q = 0; q < 8; ++q) {
        int i = tid + q*256, row = i >> 4, ch = i & 15;
        *(uint4*)(Bp + row*PITCH + ch*8) = r[q];
    }
}

__global__ void conv_w_kernel(
    const float* __restrict__ W_i, const float* __restrict__ W_f,
    const float* __restrict__ W_o, const float* __restrict__ W_u,
    const float* __restrict__ U_i, const float* __restrict__ U_f,
    const float* __restrict__ U_o, const float* __restrict__ U_u)
{
    const float* mats[8] = { W_i, W_f, W_o, W_u, U_i, U_f, U_o, U_u };
    const float* M = mats[blockIdx.x];
    __half* dst = (__half*)&g_Wh[blockIdx.x][0];
    for (int idx = threadIdx.x; idx < 16384; idx += blockDim.x)
        dst[idx] = __float2half(M[idx]);
}

// convert one fp32 row-half (opt. pair sum) into fp16 hi/lo smem
__device__ __forceinline__ void conv_row_h(__half* dh, __half* dl,
                                           int row, int half,
                                           const float* __restrict__ s0,
                                           const float* __restrict__ s1)
{
#pragma unroll
    for (int i = 0; i < 16; ++i) {
        float4 v = *(const float4*)(s0 + i*4);
        if (s1) {
            float4 w = *(const float4*)(s1 + i*4);
            v.x += w.x; v.y += w.y; v.z += w.z; v.w += w.w;
        }
        uint32_t h0,l0,h1,l1;
        split2h(v.x,v.y,h0,l0); split2h(v.z,v.w,h1,l1);
        *(uint2*)(dh + row*PITCH + half + i*4) = make_uint2(h0,h1);
        *(uint2*)(dl + row*PITCH + half + i*4) = make_uint2(l0,l1);
    }
}

#define ZERO4 { _Pragma("unroll") for (int t = 0; t < 4; ++t) \
        { dacc[t][0]=0.f; dacc[t][1]=0.f; dacc[t][2]=0.f; dacc[t][3]=0.f; } }

// ---------------------------------------------------------------------------
// Leaf: 32 leaves/block, 256 threads, 2 CTAs/SM. Gates u,i,o from x@W.
// smem: Xh,Xl (32*PITCH each) + B (128*PITCH) = 52224 B.
// ---------------------------------------------------------------------------
__global__ void __launch_bounds__(256, 2) leaf_kernel(
    const float* __restrict__ x,
    const float* __restrict__ b_i, const float* __restrict__ b_o,
    const float* __restrict__ b_u)
{
    extern __shared__ __align__(16) __half sm[];
    __half* Xh = sm;
    __half* Xl = sm + 32*PITCH;
    __half* Bp = sm + 64*PITCH;

    const int tid = threadIdx.x;
    const int w = tid >> 5, l = tid & 31;
    const int mg = w >> 2, nh = w & 3;
    const int lr = l & 15, lc = l >> 4;
    const int qr = l >> 2, qc2 = (l & 3) * 2;
    const long np = (long)((1 << DEPTH) - 1) + (long)blockIdx.x * 32;

    uint4 breg[8];
    ldB8(breg, 3, tid);                     // W_u
    if (tid < 64) {
        int row = tid >> 1, half = (tid & 1) * 64;
        conv_row_h(Xh, Xl, row, half, x + (np + row)*HH + half, nullptr);
    }
    stB8(Bp, breg, tid);
    __syncthreads();

    const uint32_t a_off = (uint32_t)((16*mg + lr)*PITCH + lc*8)*2;
    const uint32_t b_off = (uint32_t)(lr*PITCH + nh*32 + lc*8)*2;
    const uint32_t xH = smem_u32(Xh)+a_off, xL = smem_u32(Xl)+a_off;
    const uint32_t bB = smem_u32(Bp)+b_off;

    const long n0 = np + 16*mg + qr, n1 = n0 + 8;
    const int cbase = nh*32 + qc2;

    float dacc[4][4], cc[4][4];
#define SWAPB() do { __syncthreads(); stB8(Bp, breg, tid); __syncthreads(); } while (0)

    ldB8(breg, 0, tid);                     // W_i prefetch
    ZERO4; gemm_H(dacc, xH, xL, bB);        // x @ W_u
#pragma unroll
    for (int t = 0; t < 4; ++t) {
        float2 b = *(const float2*)(b_u + cbase + t*8);
        cc[t][0]=tanhx(dacc[t][0]+b.x); cc[t][1]=tanhx(dacc[t][1]+b.y);
        cc[t][2]=tanhx(dacc[t][2]+b.x); cc[t][3]=tanhx(dacc[t][3]+b.y);
    }
    SWAPB();                                // B = W_i
    ldB8(breg, 2, tid);                     // W_o prefetch
    ZERO4; gemm_H(dacc, xH, xL, bB);
#pragma unroll
    for (int t = 0; t < 4; ++t) {
        float2 b = *(const float2*)(b_i + cbase + t*8);
        cc[t][0]*=sigf(dacc[t][0]+b.x); cc[t][1]*=sigf(dacc[t][1]+b.y);
        cc[t][2]*=sigf(dacc[t][2]+b.x); cc[t][3]*=sigf(dacc[t][3]+b.y);
    }
    SWAPB();                                // B = W_o
    ZERO4; gemm_H(dacc, xH, xL, bB);
#pragma unroll
    for (int t = 0; t < 4; ++t) {
        int c = cbase + t*8;
        float2 b = *(const float2*)(b_o + c);
        float h0 = sigf(dacc[t][0]+b.x)*tanhx(cc[t][0]);
        float h1 = sigf(dacc[t][1]+b.y)*tanhx(cc[t][1]);
        float h2 = sigf(dacc[t][2]+b.x)*tanhx(cc[t][2]);
        float h3 = sigf(dacc[t][3]+b.y)*tanhx(cc[t][3]);
        *(float2*)(g_c + n0*HH + c) = make_float2(cc[t][0], cc[t][1]);
        *(float2*)(g_c + n1*HH + c) = make_float2(cc[t][2], cc[t][3]);
        *(float2*)(g_h + n0*HH + c) = make_float2(h0, h1);
        *(float2*)(g_h + n1*HH + c) = make_float2(h2, h3);
    }
#undef SWAPB
}

// ---------------------------------------------------------------------------
// Tensor level kernel: 32 parents/block, 256 threads, 2 CTAs/SM.
// A slots: X, SUM(h0+h1), S1(h1), fp16 hi/lo. 9 gemm units, 8 B stages.
// smem: 6*32*PITCH + 128*PITCH = 87040 B.
// ---------------------------------------------------------------------------
__global__ void __launch_bounds__(256, 2) tlevel_kernel(
    int sl, const float* __restrict__ x,
    const float* __restrict__ b_i, const float* __restrict__ b_f,
    const float* __restrict__ b_o, const float* __restrict__ b_u)
{
    constexpr int AS = 32 * PITCH;
    extern __shared__ __align__(16) __half sm[];
    __half* Xh  = sm;
    __half* Xl  = sm + AS;
    __half* SUh = sm + 2*AS;
    __half* SUl = sm + 3*AS;
    __half* S1h = sm + 4*AS;
    __half* S1l = sm + 5*AS;
    __half* Bp  = sm + 6*AS;

    const int tid = threadIdx.x;
    const int w = tid >> 5, l = tid & 31;
    const int mg = w >> 2, nh = w & 3;
    const int lr = l & 15, lc = l >> 4;
    const int qr = l >> 2, qc2 = (l & 3) * 2;

    const long np = (long)sl + (long)blockIdx.x * 32;
    const long cb = 2*np + 1;

    uint4 breg[8];
    ldB8(breg, 3, tid);                     // W_u
    if (tid < 192) {
        int slot = tid >> 6;                // 0=X, 1=SUM, 2=S1
        int row  = (tid & 63) >> 1;
        int half = (tid & 1) * 64;
        if (slot == 0)
            conv_row_h(Xh, Xl, row, half, x + (np + row)*HH + half, nullptr);
        else if (slot == 1)
            conv_row_h(SUh, SUl, row, half, g_h + (cb + 2*row)*HH + half,
                                            g_h + (cb + 2*row + 1)*HH + half);
        else
            conv_row_h(S1h, S1l, row, half, g_h + (cb + 2*row + 1)*HH + half, nullptr);
    }
    stB8(Bp, breg, tid);
    __syncthreads();

    const uint32_t a_off = (uint32_t)((16*mg + lr)*PITCH + lc*8)*2;
    const uint32_t b_off = (uint32_t)(lr*PITCH + nh*32 + lc*8)*2;
    const uint32_t xH  = smem_u32(Xh)+a_off,  xL  = smem_u32(Xl)+a_off;
    const uint32_t suH = smem_u32(SUh)+a_off, suL = smem_u32(SUl)+a_off;
    const uint32_t s1H = smem_u32(S1h)+a_off, s1L = smem_u32(S1l)+a_off;
    const uint32_t bB  = smem_u32(Bp)+b_off;

    const long n0 = np + 16*mg + qr, n1 = n0 + 8;
    const int cbase = nh*32 + qc2;

    float dacc[4][4], cc[4][4], xf[4][4];
#define SWAPB() do { __syncthreads(); stB8(Bp, breg, tid); __syncthreads(); } while (0)

    // ---- u ----
    ldB8(breg, 7, tid);                     // U_u
    ZERO4; gemm_H(dacc, xH, xL, bB);
    SWAPB();                                // B = U_u
    ldB8(breg, 0, tid);                     // W_i
    gemm_H(dacc, suH, suL, bB);
#pragma unroll
    for (int t = 0; t < 4; ++t) {
        float2 b = *(const float2*)(b_u + cbase + t*8);
        cc[t][0]=tanhx(dacc[t][0]+b.x); cc[t][1]=tanhx(dacc[t][1]+b.y);
        cc[t][2]=tanhx(dacc[t][2]+b.x); cc[t][3]=tanhx(dacc[t][3]+b.y);
    }
    // ---- i ----
    SWAPB();                                // B = W_i
    ldB8(breg, 4, tid);                     // U_i
    ZERO4; gemm_H(dacc, xH, xL, bB);
    SWAPB();                                // B = U_i
    ldB8(breg, 1, tid);                     // W_f
    gemm_H(dacc, suH, suL, bB);
#pragma unroll
    for (int t = 0; t < 4; ++t) {
        float2 b = *(const float2*)(b_i + cbase + t*8);
        cc[t][0]*=sigf(dacc[t][0]+b.x); cc[t][1]*=sigf(dacc[t][1]+b.y);
        cc[t][2]*=sigf(dacc[t][2]+b.x); cc[t][3]*=sigf(dacc[t][3]+b.y);
    }
    // ---- f ----
    SWAPB();                                // B = W_f
    ldB8(breg, 5, tid);                     // U_f
    ZERO4; gemm_H(dacc, xH, xL, bB);
#pragma unroll
    for (int t = 0; t < 4; ++t) {
        float2 b = *(const float2*)(b_f + cbase + t*8);
        xf[t][0]=dacc[t][0]+b.x; xf[t][1]=dacc[t][1]+b.y;
        xf[t][2]=dacc[t][2]+b.x; xf[t][3]=dacc[t][3]+b.y;
    }
    SWAPB();                                // B = U_f
    ldB8(breg, 2, tid);                     // W_o (early: U_f used twice)
    ZERO4; gemm_H(dacc, s1H, s1L, bB);      // G1 = h1 @ U_f
#pragma unroll
    for (int t = 0; t < 4; ++t) {           // f1 pairs with child1 cell
        int c = cbase + t*8;
        float2 ca = *(const float2*)(g_c + (2*n0+2)*HH + c);
        float2 cbv = *(const float2*)(g_c + (2*n1+2)*HH + c);
        cc[t][0]+=sigf(dacc[t][0]+xf[t][0])*ca.x;
        cc[t][1]+=sigf(dacc[t][1]+xf[t][1])*ca.y;
        cc[t][2]+=sigf(dacc[t][2]+xf[t][2])*cbv.x;
        cc[t][3]+=sigf(dacc[t][3]+xf[t][3])*cbv.y;
        dacc[t][0]=-dacc[t][0]; dacc[t][1]=-dacc[t][1];
        dacc[t][2]=-dacc[t][2]; dacc[t][3]=-dacc[t][3];
    }
    gemm_H(dacc, suH, suL, bB);             // Gsum - G1 = h0 @ U_f
#pragma unroll
    for (int t = 0; t < 4; ++t) {           // f0 pairs with child0 cell
        int c = cbase + t*8;
        float2 ca = *(const float2*)(g_c + (2*n0+1)*HH + c);
        float2 cbv = *(const float2*)(g_c + (2*n1+1)*HH + c);
        cc[t][0]+=sigf(dacc[t][0]+xf[t][0])*ca.x;
        cc[t][1]+=sigf(dacc[t][1]+xf[t][1])*ca.y;
        cc[t][2]+=sigf(dacc[t][2]+xf[t][2])*cbv.x;
        cc[t][3]+=sigf(dacc[t][3]+xf[t][3])*cbv.y;
    }
    // ---- o + store ----
    SWAPB();                                // B = W_o
    ldB8(breg, 6, tid);                     // U_o
    ZERO4; gemm_H(dacc, xH, xL, bB);
    SWAPB();                                // B = U_o
    gemm_H(dacc, suH, suL, bB);
#pragma unroll
    for (int t = 0; t < 4; ++t) {
        int c = cbase + t*8;
        float2 b = *(const float2*)(b_o + c);
        float h0 = sigf(dacc[t][0]+b.x)*tanhx(cc[t][0]);
        float h1 = sigf(dacc[t][1]+b.y)*tanhx(cc[t][1]);
        float h2 = sigf(dacc[t][2]+b.x)*tanhx(cc[t][2]);
        float h3 = sigf(dacc[t][3]+b.y)*tanhx(cc[t][3]);
        *(float2*)(g_c + n0*HH + c) = make_float2(cc[t][0], cc[t][1]);
        *(float2*)(g_c + n1*HH + c) = make_float2(cc[t][2], cc[t][3]);
        *(float2*)(g_h + n0*HH + c) = make_float2(h0, h1);
        *(float2*)(g_h + n1*HH + c) = make_float2(h2, h3);
    }
#undef SWAPB
}

// ---------------------------------------------------------------------------
// Small levels (nl < 32): one parent/block, 512 threads, 9 k-split matvecs.
// ---------------------------------------------------------------------------
__global__ void __launch_bounds__(512) small_level_kernel(
    int sl, const float* __restrict__ x,
    const float* __restrict__ W_i, const float* __restrict__ b_i, const float* __restrict__ U_i,
    const float* __restrict__ W_f, const float* __restrict__ b_f, const float* __restrict__ U_f,
    const float* __restrict__ W_o, const float* __restrict__ b_o, const float* __restrict__ U_o,
    const float* __restrict__ W_u, const float* __restrict__ b_u, const float* __restrict__ U_u)
{
    extern __shared__ float smf[];
    float* hs   = smf;              // [h~ | h0 | h1 | x] x 128
    float* part = smf + 512;        // [9][4][128]

    const int t = threadIdx.x;
    const long node = sl + blockIdx.x;
    const long ch0  = 2*node + 1;

    if (t < 128) {
        float h0 = g_h[ch0*HH + t];
        float h1 = g_h[(ch0+1)*HH + t];
        hs[128+t] = h0; hs[256+t] = h1; hs[t] = h0 + h1;
        hs[384+t] = x[node*HH + t];
    }
    __syncthreads();

    const int col = t & 127;
    const int q   = t >> 7;
    const int kb  = q * 32;

#define JOB(J, S, M) { float av = 0.f; const float* s = hs + (S)*128;          \
        _Pragma("unroll 8")                                                    \
        for (int k = 0; k < 32; ++k) av += s[kb+k] * (M)[(kb+k)*HH + col];     \
        part[((J)*4 + q)*128 + col] = av; }
    JOB(0, 0, U_i) JOB(1, 0, U_o) JOB(2, 0, U_u)
    JOB(3, 1, U_f) JOB(4, 2, U_f)
    JOB(5, 3, W_i) JOB(6, 3, W_f) JOB(7, 3, W_o) JOB(8, 3, W_u)
#undef JOB
    __syncthreads();

    if (t < 128) {
#define SUMP(J) (part[((J)*4+0)*128+t] + part[((J)*4+1)*128+t] + \
                 part[((J)*4+2)*128+t] + part[((J)*4+3)*128+t])
        float yi  = SUMP(0), yo = SUMP(1), yu = SUMP(2);
        float yf0 = SUMP(3), yf1 = SUMP(4);
        float xi  = SUMP(5) + b_i[t];
        float xfv = SUMP(6) + b_f[t];
        float xo  = SUMP(7) + b_o[t];
        float xu  = SUMP(8) + b_u[t];
#undef SUMP
        float c = sigf(xi+yi)*tanhx(xu+yu)
                + sigf(xfv+yf0)*g_c[ch0*HH+t] + sigf(xfv+yf1)*g_c[(ch0+1)*HH+t];
        g_c[node*HH+t] = c;
        g_h[node*HH+t] = sigf(xo+yo)*tanhx(c);
    }
}

__global__ void out_kernel(float* __restrict__ out)
{
    int t = threadIdx.x;
    out[t] = (t < 128) ? g_h[t] : g_c[t - 128];
}

// ---------------------------------------------------------------------------
extern "C" void kernel_launch(void* const* d_in, const int* in_sizes, int n_in,
                              void* d_out, int out_size)
{
    const float* x   = (const float*)d_in[0];
    const float* W_i = (const float*)d_in[1];
    const float* b_i = (const float*)d_in[2];
    const float* U_i = (const float*)d_in[3];
    const float* W_f = (const float*)d_in[4];
    const float* b_f = (const float*)d_in[5];
    const float* U_f = (const float*)d_in[6];
    const float* W_o = (const float*)d_in[7];
    const float* b_o = (const float*)d_in[8];
    const float* U_o = (const float*)d_in[9];
    const float* W_u = (const float*)d_in[10];
    const float* b_u = (const float*)d_in[11];
    const float* U_u = (const float*)d_in[12];

    const int SMEM_T = (6*32*PITCH + 128*PITCH) * 2;    // 87040
    const int SMEM_L = (2*32*PITCH + 128*PITCH) * 2;    // 52224
    const int SMEM_S = (512 + 9*4*128) * 4;
    cudaFuncSetAttribute(tlevel_kernel, cudaFuncAttributeMaxDynamicSharedMemorySize, SMEM_T);
    cudaFuncSetAttribute(leaf_kernel,   cudaFuncAttributeMaxDynamicSharedMemorySize, SMEM_L);
    cudaFuncSetAttribute(small_level_kernel, cudaFuncAttributeMaxDynamicSharedMemorySize, SMEM_S);

    conv_w_kernel<<<8, 256>>>(W_i, W_f, W_o, W_u, U_i, U_f, U_o, U_u);

    leaf_kernel<<<(1 << DEPTH) / 32, 256, SMEM_L>>>(x, b_i, b_o, b_u);

    for (int l = DEPTH - 1; l >= 0; --l) {
        int nl = 1 << l;
        int sl = nl - 1;
        if (nl >= 32)
            tlevel_kernel<<<nl / 32, 256, SMEM_T>>>(sl, x, b_i, b_f, b_o, b_u);
        else
            small_level_kernel<<<nl, 512, SMEM_S>>>(sl, x,
                W_i, b_i, U_i, W_f, b_f, U_f, W_o, b_o, U_o, W_u, b_u, U_u);
    }

    out_kernel<<<1, 256>>>((float*)d_out);
}